// round 11
// baseline (speedup 1.0000x reference)
#include <cuda_runtime.h>
#include <math.h>
#include <stdint.h>

#define NN 50000
#define EE 1600000
#define DD 128
#define LL 5
#define GG 2048
#define BN_EPS_F 1e-5f

// ---------------- scratch (static device globals; no allocation) ----------------
__device__ float g_h[NN * DD];
__device__ float g_agg[NN * DD];
__device__ float g_t[NN * DD];
__device__ float g_z[NN * DD];
__device__ int   g_src[EE];
__device__ int   g_dst[EE];
__device__ int   g_ssrc[EE];
__device__ int   g_deg[NN];
__device__ int   g_rowptr[NN + 1];
__device__ int   g_cursor[NN];
__device__ int   g_batch[NN];
__device__ float g_pooled[GG * DD];
__device__ float g_bnsum[DD];
__device__ float g_bnsq[DD];
__device__ float g_scale[DD];
__device__ float g_shift[DD];
__device__ int   g_is32;

// ---------------- tf32 helpers (sm_80+ PTX; valid on plain sm_100 target) ----------------
__device__ __forceinline__ uint32_t f2tf32(float v) {
    uint32_t u;
    asm("cvt.rna.tf32.f32 %0, %1;" : "=r"(u) : "f"(v));
    return u;
}

__device__ __forceinline__ void mma_tf32(float* d,
    uint32_t a0, uint32_t a1, uint32_t a2, uint32_t a3,
    uint32_t b0, uint32_t b1)
{
    asm volatile(
        "mma.sync.aligned.m16n8k8.row.col.f32.tf32.tf32.f32 "
        "{%0,%1,%2,%3}, {%4,%5,%6,%7}, {%8,%9}, {%0,%1,%2,%3};"
        : "+f"(d[0]), "+f"(d[1]), "+f"(d[2]), "+f"(d[3])
        : "r"(a0), "r"(a1), "r"(a2), "r"(a3), "r"(b0), "r"(b1));
}

// ---------------- dtype detection: int64 vs int32 indices ----------------
__global__ void detect_kernel(const unsigned int* __restrict__ w) {
    __shared__ int any;
    if (threadIdx.x == 0) any = 0;
    __syncthreads();
    if (w[threadIdx.x * 2 + 1] != 0u) any = 1;
    __syncthreads();
    if (threadIdx.x == 0) g_is32 = any;
}

// converts edge_index + batch AND zeroes g_deg (folds zero_deg launch)
__global__ void convert_kernel(const void* __restrict__ ei, const void* __restrict__ batch) {
    int idx = blockIdx.x * blockDim.x + threadIdx.x;
    int stride = gridDim.x * blockDim.x;
    int is32 = g_is32;
    int total = EE + NN;
    for (int i = idx; i < total; i += stride) {
        if (i < EE) {
            if (is32) {
                const int* p = (const int*)ei;
                g_src[i] = p[i];
                g_dst[i] = p[EE + i];
            } else {
                const long long* p = (const long long*)ei;
                g_src[i] = (int)p[i];
                g_dst[i] = (int)p[EE + i];
            }
        } else {
            int n = i - EE;
            if (is32) g_batch[n] = ((const int*)batch)[n];
            else      g_batch[n] = (int)((const long long*)batch)[n];
            g_deg[n] = 0;
        }
    }
}

// ---------------- CSR build ----------------
__global__ void hist_kernel() {
    int idx = blockIdx.x * blockDim.x + threadIdx.x;
    int stride = gridDim.x * blockDim.x;
    for (int e = idx; e < EE; e += stride) atomicAdd(&g_deg[g_dst[e]], 1);
}

#define SCAN_THREADS 1024
#define SCAN_CHUNK 49
__global__ void scan_kernel() {
    __shared__ int sums[SCAN_THREADS];
    int t = threadIdx.x;
    int base = t * SCAN_CHUNK;
    int local = 0;
#pragma unroll 4
    for (int i = 0; i < SCAN_CHUNK; i++) {
        int idx = base + i;
        if (idx < NN) local += g_deg[idx];
    }
    sums[t] = local;
    __syncthreads();
    for (int off = 1; off < SCAN_THREADS; off <<= 1) {
        int v = (t >= off) ? sums[t - off] : 0;
        __syncthreads();
        sums[t] += v;
        __syncthreads();
    }
    int run = (t == 0) ? 0 : sums[t - 1];
    for (int i = 0; i < SCAN_CHUNK; i++) {
        int idx = base + i;
        if (idx < NN) {
            g_rowptr[idx] = run;
            g_cursor[idx] = run;
            run += g_deg[idx];
        }
    }
    if (t == 0) g_rowptr[NN] = sums[SCAN_THREADS - 1];
}

__global__ void reorder_kernel() {
    int idx = blockIdx.x * blockDim.x + threadIdx.x;
    int stride = gridDim.x * blockDim.x;
    for (int e = idx; e < EE; e += stride) {
        int d = g_dst[e];
        int pos = atomicAdd(&g_cursor[d], 1);
        g_ssrc[pos] = g_src[e];
    }
}

// ---------------- CSR gather aggregation ----------------
__global__ __launch_bounds__(256) void aggregate_kernel() {
    int w = (blockIdx.x * blockDim.x + threadIdx.x) >> 5;
    int lane = threadIdx.x & 31;
    if (w >= NN) return;
    int beg = g_rowptr[w];
    int end = g_rowptr[w + 1];
    const float4* hv = (const float4*)g_h;
    float4 acc = hv[(size_t)w * 32 + lane];
    int e = beg;
    for (; e + 4 <= end; e += 4) {
        int s0 = g_ssrc[e];
        int s1 = g_ssrc[e + 1];
        int s2 = g_ssrc[e + 2];
        int s3 = g_ssrc[e + 3];
        float4 a = hv[(size_t)s0 * 32 + lane];
        float4 b = hv[(size_t)s1 * 32 + lane];
        float4 c = hv[(size_t)s2 * 32 + lane];
        float4 d = hv[(size_t)s3 * 32 + lane];
        acc.x += (a.x + b.x) + (c.x + d.x);
        acc.y += (a.y + b.y) + (c.y + d.y);
        acc.z += (a.z + b.z) + (c.z + d.z);
        acc.w += (a.w + b.w) + (c.w + d.w);
    }
    for (; e < end; e++) {
        int s = g_ssrc[e];
        float4 a = hv[(size_t)s * 32 + lane];
        acc.x += a.x; acc.y += a.y; acc.z += a.z; acc.w += a.w;
    }
    ((float4*)g_agg)[(size_t)w * 32 + lane] = acc;
}

// ================= 3xTF32 mma.sync GEMM, hi/lo split staged in SMEM =================
// out[M,128] = X[M,128] @ W[128,128]^T + bias
// 256 threads = 8 warps as 4(row)x2(col); warp tile 32x64; m16n8k8 fragments.
// Dynamic SMEM: Xh, Xl, Wh, Wl each 128x36 floats (73728 B total).
// mode 0: +bias -> g_h (X=Xext); mode 1: +bias,relu -> g_t (X=g_agg, block0 zeros BN accum);
// mode 2: +bias -> g_z (X=g_t)
#define GP 36
#define TILE_F (128 * GP)
#define GEMM_SMEM (4 * TILE_F * 4)

__global__ __launch_bounds__(256, 2) void gemm_mma(
    const float* __restrict__ Xext, const float* __restrict__ W,
    const float* __restrict__ bias, int M, int mode)
{
    extern __shared__ float dsm[];
    uint32_t* Xh = (uint32_t*)dsm;
    uint32_t* Xl = Xh + TILE_F;
    uint32_t* Wh = Xh + 2 * TILE_F;
    uint32_t* Wl = Xh + 3 * TILE_F;

    int t = threadIdx.x;
    int row0 = blockIdx.x << 7;

    if (mode == 1 && blockIdx.x == 0 && t < 128) { g_bnsum[t] = 0.f; g_bnsq[t] = 0.f; }

    const float* X = (mode == 0) ? Xext : ((mode == 1) ? g_agg : g_t);
    float* out = (mode == 0) ? g_h : ((mode == 1) ? g_t : g_z);

    int wid = t >> 5;
    int lane = t & 31;
    int gid = lane >> 2;     // 0..7
    int tid4 = lane & 3;     // 0..3
    int wr = wid & 3;        // warp row: rows wr*32 .. +31
    int wc = wid >> 2;       // warp col: cols wc*64 .. +63

    float acc[2][8][4];
#pragma unroll
    for (int mt = 0; mt < 2; mt++)
#pragma unroll
        for (int nt = 0; nt < 8; nt++)
#pragma unroll
            for (int j = 0; j < 4; j++) acc[mt][nt][j] = 0.f;

    for (int kc = 0; kc < 128; kc += 32) {
        // stage + split once per element
#pragma unroll
        for (int i = 0; i < 4; i++) {
            int f = t + i * 256;
            int r = f >> 3;
            int c4 = (f & 7) << 2;
            float4 xv = make_float4(0.f, 0.f, 0.f, 0.f);
            if (row0 + r < M)
                xv = *(const float4*)(X + (size_t)(row0 + r) * DD + kc + c4);
            uint4 hi, lo;
            hi.x = f2tf32(xv.x); lo.x = f2tf32(xv.x - __uint_as_float(hi.x));
            hi.y = f2tf32(xv.y); lo.y = f2tf32(xv.y - __uint_as_float(hi.y));
            hi.z = f2tf32(xv.z); lo.z = f2tf32(xv.z - __uint_as_float(hi.z));
            hi.w = f2tf32(xv.w); lo.w = f2tf32(xv.w - __uint_as_float(hi.w));
            *(uint4*)(Xh + r * GP + c4) = hi;
            *(uint4*)(Xl + r * GP + c4) = lo;
            float4 wv = *(const float4*)(W + (size_t)r * DD + kc + c4);
            hi.x = f2tf32(wv.x); lo.x = f2tf32(wv.x - __uint_as_float(hi.x));
            hi.y = f2tf32(wv.y); lo.y = f2tf32(wv.y - __uint_as_float(hi.y));
            hi.z = f2tf32(wv.z); lo.z = f2tf32(wv.z - __uint_as_float(hi.z));
            hi.w = f2tf32(wv.w); lo.w = f2tf32(wv.w - __uint_as_float(hi.w));
            *(uint4*)(Wh + r * GP + c4) = hi;
            *(uint4*)(Wl + r * GP + c4) = lo;
        }
        __syncthreads();

#pragma unroll
        for (int ks = 0; ks < 4; ks++) {
            int k0 = ks * 8;
            uint32_t ah[2][4], al[2][4];
#pragma unroll
            for (int mt = 0; mt < 2; mt++) {
                int rb = wr * 32 + mt * 16 + gid;
                ah[mt][0] = Xh[rb * GP + k0 + tid4];
                ah[mt][1] = Xh[(rb + 8) * GP + k0 + tid4];
                ah[mt][2] = Xh[rb * GP + k0 + tid4 + 4];
                ah[mt][3] = Xh[(rb + 8) * GP + k0 + tid4 + 4];
                al[mt][0] = Xl[rb * GP + k0 + tid4];
                al[mt][1] = Xl[(rb + 8) * GP + k0 + tid4];
                al[mt][2] = Xl[rb * GP + k0 + tid4 + 4];
                al[mt][3] = Xl[(rb + 8) * GP + k0 + tid4 + 4];
            }
#pragma unroll
            for (int nt = 0; nt < 8; nt++) {
                int cb = wc * 64 + nt * 8 + gid;
                uint32_t bh0 = Wh[cb * GP + k0 + tid4];
                uint32_t bh1 = Wh[cb * GP + k0 + tid4 + 4];
                uint32_t bl0 = Wl[cb * GP + k0 + tid4];
                uint32_t bl1 = Wl[cb * GP + k0 + tid4 + 4];
#pragma unroll
                for (int mt = 0; mt < 2; mt++) {
                    mma_tf32(acc[mt][nt], ah[mt][0], ah[mt][1], ah[mt][2], ah[mt][3], bh0, bh1);
                    mma_tf32(acc[mt][nt], ah[mt][0], ah[mt][1], ah[mt][2], ah[mt][3], bl0, bl1);
                    mma_tf32(acc[mt][nt], al[mt][0], al[mt][1], al[mt][2], al[mt][3], bh0, bh1);
                }
            }
        }
        __syncthreads();
    }

    // epilogue: c0:(r,c) c1:(r,c+1) c2:(r+8,c) c3:(r+8,c+1)
#pragma unroll
    for (int mt = 0; mt < 2; mt++) {
        int r = row0 + wr * 32 + mt * 16 + gid;
#pragma unroll
        for (int nt = 0; nt < 8; nt++) {
            int c = wc * 64 + nt * 8 + tid4 * 2;
            float2 bv = *(const float2*)(bias + c);
            float2 v0, v1;
            v0.x = acc[mt][nt][0] + bv.x;
            v0.y = acc[mt][nt][1] + bv.y;
            v1.x = acc[mt][nt][2] + bv.x;
            v1.y = acc[mt][nt][3] + bv.y;
            if (mode == 1) {
                v0.x = fmaxf(v0.x, 0.f); v0.y = fmaxf(v0.y, 0.f);
                v1.x = fmaxf(v1.x, 0.f); v1.y = fmaxf(v1.y, 0.f);
            }
            if (r < M)     *(float2*)(out + (size_t)r * DD + c) = v0;
            if (r + 8 < M) *(float2*)(out + (size_t)(r + 8) * DD + c) = v1;
        }
    }
}

// ---------------- BN stats: column sums over g_z (coalesced) ----------------
#define BN_ROWS 256
__global__ void bn_stats_kernel() {
    int t = threadIdx.x;   // column
    int r0 = blockIdx.x * BN_ROWS;
    int rend = min(r0 + BN_ROWS, NN);
    float sum = 0.f, sq = 0.f;
    for (int r = r0; r < rend; r++) {
        float v = g_z[(size_t)r * DD + t];
        sum += v; sq += v * v;
    }
    atomicAdd(&g_bnsum[t], sum);
    atomicAdd(&g_bnsq[t], sq);
}

// ---------------- BN finalize ----------------
__global__ void bn_finalize_kernel(const float* __restrict__ gamma, const float* __restrict__ beta) {
    int t = threadIdx.x;
    float mu = g_bnsum[t] * (1.f / NN);
    float var = g_bnsq[t] * (1.f / NN) - mu * mu;
    float sc = gamma[t] * rsqrtf(var + BN_EPS_F);
    g_scale[t] = sc;
    g_shift[t] = beta[t] - mu * sc;
}

// ---------------- BN apply + relu ----------------
__global__ void bn_apply_kernel() {
    int idx = blockIdx.x * blockDim.x + threadIdx.x;
    int stride = gridDim.x * blockDim.x;
    int total = NN * DD / 4;
    for (int i = idx; i < total; i += stride) {
        int cb = (i << 2) & (DD - 1);
        float4 z = *(const float4*)(&g_z[(size_t)i * 4]);
        float4 sc = *(const float4*)(&g_scale[cb]);
        float4 sh = *(const float4*)(&g_shift[cb]);
        float4 r;
        r.x = fmaxf(fmaf(z.x, sc.x, sh.x), 0.f);
        r.y = fmaxf(fmaf(z.y, sc.y, sh.y), 0.f);
        r.z = fmaxf(fmaf(z.z, sc.z, sh.z), 0.f);
        r.w = fmaxf(fmaf(z.w, sc.w, sh.w), 0.f);
        *(float4*)(&g_h[(size_t)i * 4]) = r;
    }
}

// ---------------- graph pooling ----------------
__global__ void zero_pooled_kernel() {
    int idx = blockIdx.x * blockDim.x + threadIdx.x;
    int stride = gridDim.x * blockDim.x;
    for (int i = idx; i < GG * DD; i += stride) g_pooled[i] = 0.f;
}

__global__ void pool_kernel() {
    int lane = threadIdx.x & 31;
    int w = (blockIdx.x * blockDim.x + threadIdx.x) >> 5;
    int nw = (gridDim.x * blockDim.x) >> 5;
    for (int n = w; n < NN; n += nw) {
        int g = g_batch[n];
        float4 v = *(const float4*)(g_h + (size_t)n * DD + (lane << 2));
        float* p = g_pooled + (size_t)g * DD + (lane << 2);
        atomicAdd(p + 0, v.x);
        atomicAdd(p + 1, v.y);
        atomicAdd(p + 2, v.z);
        atomicAdd(p + 3, v.w);
    }
}

// ---------------- final MLP ----------------
__global__ void final_kernel(const float* __restrict__ w1, const float* __restrict__ b1,
                             const float* __restrict__ w2, const float* __restrict__ b2,
                             float* __restrict__ out)
{
    __shared__ float row[DD];
    __shared__ float wsum[4];
    int g = blockIdx.x;
    int t = threadIdx.x;
    int lane = t & 31, warp = t >> 5;

    row[t] = g_pooled[(size_t)g * DD + t];
    __syncthreads();

    float4 r = *(const float4*)(&row[lane * 4]);
    float accum = 0.f;
    for (int c = warp; c < DD; c += 4) {
        float4 a = *(const float4*)(w1 + (size_t)c * DD + lane * 4);
        float p = a.x * r.x + a.y * r.y + a.z * r.z + a.w * r.w;
#pragma unroll
        for (int off = 16; off; off >>= 1) p += __shfl_down_sync(0xffffffffu, p, off);
        if (lane == 0) accum += fmaxf(p + b1[c], 0.f) * w2[c];
    }
    if (lane == 0) wsum[warp] = accum;
    __syncthreads();
    if (t == 0) out[g] = wsum[0] + wsum[1] + wsum[2] + wsum[3] + b2[0];
}

// ---------------- launch ----------------
extern "C" void kernel_launch(void* const* d_in, const int* in_sizes, int n_in,
                              void* d_out, int out_size)
{
    const float* x        = (const float*)d_in[0];
    const void*  ei       = d_in[1];
    const void*  batch    = d_in[2];
    const float* lin_w    = (const float*)d_in[3];
    const float* lin_b    = (const float*)d_in[4];
    const float* conv_w1  = (const float*)d_in[5];
    const float* conv_b1  = (const float*)d_in[6];
    const float* conv_w2  = (const float*)d_in[7];
    const float* conv_b2  = (const float*)d_in[8];
    const float* bn_gamma = (const float*)d_in[9];
    const float* bn_beta  = (const float*)d_in[10];
    const float* mlp_w1   = (const float*)d_in[11];
    const float* mlp_b1   = (const float*)d_in[12];
    const float* mlp_w2   = (const float*)d_in[13];
    const float* mlp_b2   = (const float*)d_in[14];
    float* out = (float*)d_out;

    // one-time opt-in for >48KB dynamic smem (host attribute; set pre-capture on first call)
    static int smem_set = 0;
    if (!smem_set) {
        cudaFuncSetAttribute(gemm_mma, cudaFuncAttributeMaxDynamicSharedMemorySize, GEMM_SMEM);
        smem_set = 1;
    }

    const int gblocks = (NN + 127) / 128;   // 391

    // launch order puts gemm_mma at slot 6 for the ncu -s 5 -c 1 window
    detect_kernel<<<1, 128>>>((const unsigned int*)ei);         // 1
    convert_kernel<<<4096, 256>>>(ei, batch);                   // 2 (also zeroes g_deg)
    hist_kernel<<<2048, 256>>>();                               // 3
    scan_kernel<<<1, SCAN_THREADS>>>();                         // 4
    reorder_kernel<<<2048, 256>>>();                            // 5
    gemm_mma<<<gblocks, 256, GEMM_SMEM>>>(x, lin_w, lin_b, NN, 0);  // 6 <- profiled

    const int ablocks = (NN * 32 + 255) / 256;
    const int sblocks = (NN + BN_ROWS - 1) / BN_ROWS;
    for (int i = 0; i < LL; i++) {
        aggregate_kernel<<<ablocks, 256>>>();
        gemm_mma<<<gblocks, 256, GEMM_SMEM>>>(nullptr, conv_w1 + (size_t)i * DD * DD, conv_b1 + i * DD, NN, 1);
        gemm_mma<<<gblocks, 256, GEMM_SMEM>>>(nullptr, conv_w2 + (size_t)i * DD * DD, conv_b2 + i * DD, NN, 2);
        bn_stats_kernel<<<sblocks, 128>>>();
        bn_finalize_kernel<<<1, 128>>>(bn_gamma + i * DD, bn_beta + i * DD);
        bn_apply_kernel<<<4096, 256>>>();
    }

    zero_pooled_kernel<<<1024, 256>>>();
    pool_kernel<<<1024, 256>>>();
    final_kernel<<<GG, 128>>>(mlp_w1, mlp_b1, mlp_w2, mlp_b2, out);
}

// round 15
// speedup vs baseline: 1.0825x; 1.0825x over previous
#include <cuda_runtime.h>
#include <math.h>
#include <stdint.h>

#define NN 50000
#define EE 1600000
#define DD 128
#define LL 5
#define GG 2048
#define BN_EPS_F 1e-5f

// ---------------- scratch (static device globals; no allocation) ----------------
__device__ float g_h[NN * DD];
__device__ float g_agg[NN * DD];
__device__ float g_t[NN * DD];
__device__ float g_z[NN * DD];
__device__ int   g_src[EE];
__device__ int   g_dst[EE];
__device__ int   g_ssrc[EE];
__device__ int   g_deg[NN];
__device__ int   g_rowptr[NN + 1];
__device__ int   g_cursor[NN];
__device__ int   g_batch[NN];
__device__ float g_pooled[GG * DD];
__device__ float g_bnsum[DD];
__device__ float g_bnsq[DD];
__device__ float g_scale[DD];
__device__ float g_shift[DD];
__device__ int   g_is32;

// ---------------- tf32 helpers (sm_80+ PTX; valid on plain sm_100 target) ----------------
__device__ __forceinline__ uint32_t f2tf32(float v) {
    uint32_t u;
    asm("cvt.rna.tf32.f32 %0, %1;" : "=r"(u) : "f"(v));
    return u;
}

__device__ __forceinline__ void mma_tf32(float* d,
    uint32_t a0, uint32_t a1, uint32_t a2, uint32_t a3,
    uint32_t b0, uint32_t b1)
{
    asm volatile(
        "mma.sync.aligned.m16n8k8.row.col.f32.tf32.tf32.f32 "
        "{%0,%1,%2,%3}, {%4,%5,%6,%7}, {%8,%9}, {%0,%1,%2,%3};"
        : "+f"(d[0]), "+f"(d[1]), "+f"(d[2]), "+f"(d[3])
        : "r"(a0), "r"(a1), "r"(a2), "r"(a3), "r"(b0), "r"(b1));
}

// ---------------- dtype detection ----------------
__global__ void detect_kernel(const unsigned int* __restrict__ w) {
    __shared__ int any;
    if (threadIdx.x == 0) any = 0;
    __syncthreads();
    if (w[threadIdx.x * 2 + 1] != 0u) any = 1;
    __syncthreads();
    if (threadIdx.x == 0) g_is32 = any;
}

__global__ void zero_deg_kernel() {
    int idx = blockIdx.x * blockDim.x + threadIdx.x;
    if (idx < NN) g_deg[idx] = 0;
}

// converts edge_index + batch AND histograms dst into g_deg (fused hist)
__global__ void convert_kernel(const void* __restrict__ ei, const void* __restrict__ batch) {
    int idx = blockIdx.x * blockDim.x + threadIdx.x;
    int stride = gridDim.x * blockDim.x;
    int is32 = g_is32;
    int total = EE + NN;
    for (int i = idx; i < total; i += stride) {
        if (i < EE) {
            int s, d;
            if (is32) {
                const int* p = (const int*)ei;
                s = p[i]; d = p[EE + i];
            } else {
                const long long* p = (const long long*)ei;
                s = (int)p[i]; d = (int)p[EE + i];
            }
            g_src[i] = s;
            g_dst[i] = d;
            atomicAdd(&g_deg[d], 1);
        } else {
            int n = i - EE;
            if (is32) g_batch[n] = ((const int*)batch)[n];
            else      g_batch[n] = (int)((const long long*)batch)[n];
        }
    }
}

// ---------------- pipelined single-block scan: coalesced + warp shuffles ----------------
#define SCAN_THREADS 1024
__global__ void scan_kernel() {
    __shared__ int wsum[32];
    __shared__ int carry_s;
    int t = threadIdx.x, lane = t & 31, wp = t >> 5;
    if (t == 0) carry_s = 0;
    __syncthreads();

    int v_next = (t < NN) ? g_deg[t] : 0;
    for (int base = 0; base < NN; base += SCAN_THREADS) {
        int v = v_next;
        int ni = base + SCAN_THREADS + t;
        if (base + SCAN_THREADS < NN)
            v_next = (ni < NN) ? g_deg[ni] : 0;   // prefetch overlaps scan math

        // inclusive warp scan
        int s = v;
#pragma unroll
        for (int o = 1; o < 32; o <<= 1) {
            int u = __shfl_up_sync(0xffffffffu, s, o);
            if (lane >= o) s += u;
        }
        if (lane == 31) wsum[wp] = s;
        __syncthreads();
        if (wp == 0) {
            int x = wsum[lane];
#pragma unroll
            for (int o = 1; o < 32; o <<= 1) {
                int u = __shfl_up_sync(0xffffffffu, x, o);
                if (lane >= o) x += u;
            }
            wsum[lane] = x;   // inclusive cross-warp sums
        }
        __syncthreads();

        int carry_blk = carry_s;
        int excl = carry_blk + (wp ? wsum[wp - 1] : 0) + s - v;
        int idx = base + t;
        if (idx < NN) { g_rowptr[idx] = excl; g_cursor[idx] = excl; }
        __syncthreads();                       // everyone has read carry_s
        if (t == SCAN_THREADS - 1) carry_s = carry_blk + wsum[31];
        __syncthreads();
    }
    if (t == 0) g_rowptr[NN] = carry_s;
}

__global__ void reorder_kernel() {
    int idx = blockIdx.x * blockDim.x + threadIdx.x;
    int stride = gridDim.x * blockDim.x;
    for (int e = idx; e < EE; e += stride) {
        int d = g_dst[e];
        int pos = atomicAdd(&g_cursor[d], 1);
        g_ssrc[pos] = g_src[e];
    }
}

// ---------------- CSR gather aggregation ----------------
__global__ __launch_bounds__(256) void aggregate_kernel() {
    int w = (blockIdx.x * blockDim.x + threadIdx.x) >> 5;
    int lane = threadIdx.x & 31;
    if (w >= NN) return;
    int beg = g_rowptr[w];
    int end = g_rowptr[w + 1];
    const float4* hv = (const float4*)g_h;
    float4 acc = hv[(size_t)w * 32 + lane];
    int e = beg;
    for (; e + 4 <= end; e += 4) {
        int s0 = g_ssrc[e];
        int s1 = g_ssrc[e + 1];
        int s2 = g_ssrc[e + 2];
        int s3 = g_ssrc[e + 3];
        float4 a = hv[(size_t)s0 * 32 + lane];
        float4 b = hv[(size_t)s1 * 32 + lane];
        float4 c = hv[(size_t)s2 * 32 + lane];
        float4 d = hv[(size_t)s3 * 32 + lane];
        acc.x += (a.x + b.x) + (c.x + d.x);
        acc.y += (a.y + b.y) + (c.y + d.y);
        acc.z += (a.z + b.z) + (c.z + d.z);
        acc.w += (a.w + b.w) + (c.w + d.w);
    }
    for (; e < end; e++) {
        int s = g_ssrc[e];
        float4 a = hv[(size_t)s * 32 + lane];
        acc.x += a.x; acc.y += a.y; acc.z += a.z; acc.w += a.w;
    }
    ((float4*)g_agg)[(size_t)w * 32 + lane] = acc;
}

// ================= 3xTF32 mma.sync GEMM, hi/lo split staged in SMEM =================
#define GP 36
#define TILE_F (128 * GP)
#define GEMM_SMEM (4 * TILE_F * 4)

__global__ __launch_bounds__(256, 2) void gemm_mma(
    const float* __restrict__ Xext, const float* __restrict__ W,
    const float* __restrict__ bias, int M, int mode)
{
    extern __shared__ float dsm[];
    uint32_t* Xh = (uint32_t*)dsm;
    uint32_t* Xl = Xh + TILE_F;
    uint32_t* Wh = Xh + 2 * TILE_F;
    uint32_t* Wl = Xh + 3 * TILE_F;

    int t = threadIdx.x;
    int row0 = blockIdx.x << 7;

    if (mode == 1 && blockIdx.x == 0 && t < 128) { g_bnsum[t] = 0.f; g_bnsq[t] = 0.f; }

    const float* X = (mode == 0) ? Xext : ((mode == 1) ? g_agg : g_t);
    float* out = (mode == 0) ? g_h : ((mode == 1) ? g_t : g_z);

    int wid = t >> 5;
    int lane = t & 31;
    int gid = lane >> 2;
    int tid4 = lane & 3;
    int wr = wid & 3;
    int wc = wid >> 2;

    float acc[2][8][4];
#pragma unroll
    for (int mt = 0; mt < 2; mt++)
#pragma unroll
        for (int nt = 0; nt < 8; nt++)
#pragma unroll
            for (int j = 0; j < 4; j++) acc[mt][nt][j] = 0.f;

    for (int kc = 0; kc < 128; kc += 32) {
#pragma unroll
        for (int i = 0; i < 4; i++) {
            int f = t + i * 256;
            int r = f >> 3;
            int c4 = (f & 7) << 2;
            float4 xv = make_float4(0.f, 0.f, 0.f, 0.f);
            if (row0 + r < M)
                xv = *(const float4*)(X + (size_t)(row0 + r) * DD + kc + c4);
            uint4 hi, lo;
            hi.x = f2tf32(xv.x); lo.x = f2tf32(xv.x - __uint_as_float(hi.x));
            hi.y = f2tf32(xv.y); lo.y = f2tf32(xv.y - __uint_as_float(hi.y));
            hi.z = f2tf32(xv.z); lo.z = f2tf32(xv.z - __uint_as_float(hi.z));
            hi.w = f2tf32(xv.w); lo.w = f2tf32(xv.w - __uint_as_float(hi.w));
            *(uint4*)(Xh + r * GP + c4) = hi;
            *(uint4*)(Xl + r * GP + c4) = lo;
            float4 wv = *(const float4*)(W + (size_t)r * DD + kc + c4);
            hi.x = f2tf32(wv.x); lo.x = f2tf32(wv.x - __uint_as_float(hi.x));
            hi.y = f2tf32(wv.y); lo.y = f2tf32(wv.y - __uint_as_float(hi.y));
            hi.z = f2tf32(wv.z); lo.z = f2tf32(wv.z - __uint_as_float(hi.z));
            hi.w = f2tf32(wv.w); lo.w = f2tf32(wv.w - __uint_as_float(hi.w));
            *(uint4*)(Wh + r * GP + c4) = hi;
            *(uint4*)(Wl + r * GP + c4) = lo;
        }
        __syncthreads();

#pragma unroll
        for (int ks = 0; ks < 4; ks++) {
            int k0 = ks * 8;
            uint32_t ah[2][4], al[2][4];
#pragma unroll
            for (int mt = 0; mt < 2; mt++) {
                int rb = wr * 32 + mt * 16 + gid;
                ah[mt][0] = Xh[rb * GP + k0 + tid4];
                ah[mt][1] = Xh[(rb + 8) * GP + k0 + tid4];
                ah[mt][2] = Xh[rb * GP + k0 + tid4 + 4];
                ah[mt][3] = Xh[(rb + 8) * GP + k0 + tid4 + 4];
                al[mt][0] = Xl[rb * GP + k0 + tid4];
                al[mt][1] = Xl[(rb + 8) * GP + k0 + tid4];
                al[mt][2] = Xl[rb * GP + k0 + tid4 + 4];
                al[mt][3] = Xl[(rb + 8) * GP + k0 + tid4 + 4];
            }
#pragma unroll
            for (int nt = 0; nt < 8; nt++) {
                int cb = wc * 64 + nt * 8 + gid;
                uint32_t bh0 = Wh[cb * GP + k0 + tid4];
                uint32_t bh1 = Wh[cb * GP + k0 + tid4 + 4];
                uint32_t bl0 = Wl[cb * GP + k0 + tid4];
                uint32_t bl1 = Wl[cb * GP + k0 + tid4 + 4];
#pragma unroll
                for (int mt = 0; mt < 2; mt++) {
                    mma_tf32(acc[mt][nt], ah[mt][0], ah[mt][1], ah[mt][2], ah[mt][3], bh0, bh1);
                    mma_tf32(acc[mt][nt], ah[mt][0], ah[mt][1], ah[mt][2], ah[mt][3], bl0, bl1);
                    mma_tf32(acc[mt][nt], al[mt][0], al[mt][1], al[mt][2], al[mt][3], bh0, bh1);
                }
            }
        }
        __syncthreads();
    }

#pragma unroll
    for (int mt = 0; mt < 2; mt++) {
        int r = row0 + wr * 32 + mt * 16 + gid;
#pragma unroll
        for (int nt = 0; nt < 8; nt++) {
            int c = wc * 64 + nt * 8 + tid4 * 2;
            float2 bv = *(const float2*)(bias + c);
            float2 v0, v1;
            v0.x = acc[mt][nt][0] + bv.x;
            v0.y = acc[mt][nt][1] + bv.y;
            v1.x = acc[mt][nt][2] + bv.x;
            v1.y = acc[mt][nt][3] + bv.y;
            if (mode == 1) {
                v0.x = fmaxf(v0.x, 0.f); v0.y = fmaxf(v0.y, 0.f);
                v1.x = fmaxf(v1.x, 0.f); v1.y = fmaxf(v1.y, 0.f);
            }
            if (r < M)     *(float2*)(out + (size_t)r * DD + c) = v0;
            if (r + 8 < M) *(float2*)(out + (size_t)(r + 8) * DD + c) = v1;
        }
    }
}

// ---------------- BN stats ----------------
#define BN_ROWS 256
__global__ void bn_stats_kernel() {
    int t = threadIdx.x;
    int r0 = blockIdx.x * BN_ROWS;
    int rend = min(r0 + BN_ROWS, NN);
    float sum = 0.f, sq = 0.f;
    for (int r = r0; r < rend; r++) {
        float v = g_z[(size_t)r * DD + t];
        sum += v; sq += v * v;
    }
    atomicAdd(&g_bnsum[t], sum);
    atomicAdd(&g_bnsq[t], sq);
}

__global__ void bn_finalize_kernel(const float* __restrict__ gamma, const float* __restrict__ beta) {
    int t = threadIdx.x;
    float mu = g_bnsum[t] * (1.f / NN);
    float var = g_bnsq[t] * (1.f / NN) - mu * mu;
    float sc = gamma[t] * rsqrtf(var + BN_EPS_F);
    g_scale[t] = sc;
    g_shift[t] = beta[t] - mu * sc;
}

__global__ void bn_apply_kernel() {
    int idx = blockIdx.x * blockDim.x + threadIdx.x;
    int stride = gridDim.x * blockDim.x;
    int total = NN * DD / 4;
    for (int i = idx; i < total; i += stride) {
        int cb = (i << 2) & (DD - 1);
        float4 z = *(const float4*)(&g_z[(size_t)i * 4]);
        float4 sc = *(const float4*)(&g_scale[cb]);
        float4 sh = *(const float4*)(&g_shift[cb]);
        float4 r;
        r.x = fmaxf(fmaf(z.x, sc.x, sh.x), 0.f);
        r.y = fmaxf(fmaf(z.y, sc.y, sh.y), 0.f);
        r.z = fmaxf(fmaf(z.z, sc.z, sh.z), 0.f);
        r.w = fmaxf(fmaf(z.w, sc.w, sh.w), 0.f);
        *(float4*)(&g_h[(size_t)i * 4]) = r;
    }
}

// ---------------- graph pooling ----------------
__global__ void zero_pooled_kernel() {
    int idx = blockIdx.x * blockDim.x + threadIdx.x;
    int stride = gridDim.x * blockDim.x;
    for (int i = idx; i < GG * DD; i += stride) g_pooled[i] = 0.f;
}

__global__ void pool_kernel() {
    int lane = threadIdx.x & 31;
    int w = (blockIdx.x * blockDim.x + threadIdx.x) >> 5;
    int nw = (gridDim.x * blockDim.x) >> 5;
    for (int n = w; n < NN; n += nw) {
        int g = g_batch[n];
        float4 v = *(const float4*)(g_h + (size_t)n * DD + (lane << 2));
        float* p = g_pooled + (size_t)g * DD + (lane << 2);
        atomicAdd(p + 0, v.x);
        atomicAdd(p + 1, v.y);
        atomicAdd(p + 2, v.z);
        atomicAdd(p + 3, v.w);
    }
}

// ---------------- final MLP ----------------
__global__ void final_kernel(const float* __restrict__ w1, const float* __restrict__ b1,
                             const float* __restrict__ w2, const float* __restrict__ b2,
                             float* __restrict__ out)
{
    __shared__ float row[DD];
    __shared__ float wsum[4];
    int g = blockIdx.x;
    int t = threadIdx.x;
    int lane = t & 31, warp = t >> 5;

    row[t] = g_pooled[(size_t)g * DD + t];
    __syncthreads();

    float4 r = *(const float4*)(&row[lane * 4]);
    float accum = 0.f;
    for (int c = warp; c < DD; c += 4) {
        float4 a = *(const float4*)(w1 + (size_t)c * DD + lane * 4);
        float p = a.x * r.x + a.y * r.y + a.z * r.z + a.w * r.w;
#pragma unroll
        for (int off = 16; off; off >>= 1) p += __shfl_down_sync(0xffffffffu, p, off);
        if (lane == 0) accum += fmaxf(p + b1[c], 0.f) * w2[c];
    }
    if (lane == 0) wsum[warp] = accum;
    __syncthreads();
    if (t == 0) out[g] = wsum[0] + wsum[1] + wsum[2] + wsum[3] + b2[0];
}

// ---------------- launch ----------------
extern "C" void kernel_launch(void* const* d_in, const int* in_sizes, int n_in,
                              void* d_out, int out_size)
{
    const float* x        = (const float*)d_in[0];
    const void*  ei       = d_in[1];
    const void*  batch    = d_in[2];
    const float* lin_w    = (const float*)d_in[3];
    const float* lin_b    = (const float*)d_in[4];
    const float* conv_w1  = (const float*)d_in[5];
    const float* conv_b1  = (const float*)d_in[6];
    const float* conv_w2  = (const float*)d_in[7];
    const float* conv_b2  = (const float*)d_in[8];
    const float* bn_gamma = (const float*)d_in[9];
    const float* bn_beta  = (const float*)d_in[10];
    const float* mlp_w1   = (const float*)d_in[11];
    const float* mlp_b1   = (const float*)d_in[12];
    const float* mlp_w2   = (const float*)d_in[13];
    const float* mlp_b2   = (const float*)d_in[14];
    float* out = (float*)d_out;

    static int smem_set = 0;
    if (!smem_set) {
        cudaFuncSetAttribute(gemm_mma, cudaFuncAttributeMaxDynamicSharedMemorySize, GEMM_SMEM);
        smem_set = 1;
    }

    const int gblocks = (NN + 127) / 128;   // 391

    detect_kernel<<<1, 128>>>((const unsigned int*)ei);             // 1
    zero_deg_kernel<<<(NN + 255) / 256, 256>>>();                   // 2
    convert_kernel<<<4096, 256>>>(ei, batch);                       // 3 (fused hist)
    scan_kernel<<<1, SCAN_THREADS>>>();                             // 4
    reorder_kernel<<<2048, 256>>>();                                // 5
    gemm_mma<<<gblocks, 256, GEMM_SMEM>>>(x, lin_w, lin_b, NN, 0);  // 6

    const int ablocks = (NN * 32 + 255) / 256;
    const int sblocks = (NN + BN_ROWS - 1) / BN_ROWS;
    for (int i = 0; i < LL; i++) {
        aggregate_kernel<<<ablocks, 256>>>();
        gemm_mma<<<gblocks, 256, GEMM_SMEM>>>(nullptr, conv_w1 + (size_t)i * DD * DD, conv_b1 + i * DD, NN, 1);
        gemm_mma<<<gblocks, 256, GEMM_SMEM>>>(nullptr, conv_w2 + (size_t)i * DD * DD, conv_b2 + i * DD, NN, 2);
        bn_stats_kernel<<<sblocks, 128>>>();
        bn_finalize_kernel<<<1, 128>>>(bn_gamma + i * DD, bn_beta + i * DD);
        bn_apply_kernel<<<4096, 256>>>();
    }

    zero_pooled_kernel<<<1024, 256>>>();
    pool_kernel<<<1024, 256>>>();
    final_kernel<<<GG, 128>>>(mlp_w1, mlp_b1, mlp_w2, mlp_b2, out);
}

// round 16
// speedup vs baseline: 1.1371x; 1.0504x over previous
#include <cuda_runtime.h>
#include <math.h>
#include <stdint.h>

#define NN 50000
#define EE 1600000
#define DD 128
#define LL 5
#define GG 2048
#define BN_EPS_F 1e-5f

#define DEG_PAD 57344          // 1024 threads * 8 elems * 7 iters

// ---------------- scratch (static device globals; no allocation) ----------------
__device__ float g_h[NN * DD];
__device__ float g_agg[NN * DD];
__device__ float g_t[NN * DD];
__device__ float g_z[NN * DD];
__device__ int   g_src[EE];
__device__ int   g_dst[EE];
__device__ int   g_ssrc[EE];
__device__ int   g_deg[DEG_PAD];
__device__ int   g_rowptr[DEG_PAD + 8];
__device__ int   g_cursor[DEG_PAD];
__device__ int   g_batch[NN];
__device__ float g_pooled[GG * DD];
__device__ float g_bnsum[DD];
__device__ float g_bnsq[DD];
__device__ int   g_is32;

// ---------------- tf32 helpers ----------------
__device__ __forceinline__ uint32_t f2tf32(float v) {
    uint32_t u;
    asm("cvt.rna.tf32.f32 %0, %1;" : "=r"(u) : "f"(v));
    return u;
}

__device__ __forceinline__ void mma_tf32(float* d,
    uint32_t a0, uint32_t a1, uint32_t a2, uint32_t a3,
    uint32_t b0, uint32_t b1)
{
    asm volatile(
        "mma.sync.aligned.m16n8k8.row.col.f32.tf32.tf32.f32 "
        "{%0,%1,%2,%3}, {%4,%5,%6,%7}, {%8,%9}, {%0,%1,%2,%3};"
        : "+f"(d[0]), "+f"(d[1]), "+f"(d[2]), "+f"(d[3])
        : "r"(a0), "r"(a1), "r"(a2), "r"(a3), "r"(b0), "r"(b1));
}

// ---------------- dtype detection ----------------
__global__ void detect_kernel(const unsigned int* __restrict__ w) {
    __shared__ int any;
    if (threadIdx.x == 0) any = 0;
    __syncthreads();
    if (w[threadIdx.x * 2 + 1] != 0u) any = 1;
    __syncthreads();
    if (threadIdx.x == 0) g_is32 = any;
}

__global__ void zero_deg_kernel() {
    int idx = blockIdx.x * blockDim.x + threadIdx.x;
    if (idx < DEG_PAD) g_deg[idx] = 0;
}

// converts edge_index + batch AND histograms dst into g_deg
__global__ void convert_kernel(const void* __restrict__ ei, const void* __restrict__ batch) {
    int idx = blockIdx.x * blockDim.x + threadIdx.x;
    int stride = gridDim.x * blockDim.x;
    int is32 = g_is32;
    int total = EE + NN;
    for (int i = idx; i < total; i += stride) {
        if (i < EE) {
            int s, d;
            if (is32) {
                const int* p = (const int*)ei;
                s = p[i]; d = p[EE + i];
            } else {
                const long long* p = (const long long*)ei;
                s = (int)p[i]; d = (int)p[EE + i];
            }
            g_src[i] = s;
            g_dst[i] = d;
            atomicAdd(&g_deg[d], 1);
        } else {
            int n = i - EE;
            if (is32) g_batch[n] = ((const int*)batch)[n];
            else      g_batch[n] = (int)((const long long*)batch)[n];
        }
    }
}

// ---------------- scan v3: 8 elems/thread, int4 loads/stores, 7 iterations ----------------
#define SCAN_THREADS 1024
#define SCAN_ITERS 7
__global__ void scan_kernel() {
    __shared__ int wsum[32];
    __shared__ int carry_s;
    int t = threadIdx.x, lane = t & 31, wp = t >> 5;
    if (t == 0) carry_s = 0;
    __syncthreads();

#pragma unroll
    for (int iter = 0; iter < SCAN_ITERS; iter++) {
        int base = iter * (SCAN_THREADS * 8);
        int o = base + t * 8;
        int4 a = *(const int4*)(g_deg + o);
        int4 b = *(const int4*)(g_deg + o + 4);
        int p0 = a.x;
        int p1 = p0 + a.y;
        int p2 = p1 + a.z;
        int p3 = p2 + a.w;
        int p4 = p3 + b.x;
        int p5 = p4 + b.y;
        int p6 = p5 + b.z;
        int T  = p6 + b.w;

        // inclusive warp scan of per-thread totals
        int s = T;
#pragma unroll
        for (int of = 1; of < 32; of <<= 1) {
            int u = __shfl_up_sync(0xffffffffu, s, of);
            if (lane >= of) s += u;
        }
        if (lane == 31) wsum[wp] = s;
        __syncthreads();
        if (wp == 0) {
            int x = wsum[lane];
#pragma unroll
            for (int of = 1; of < 32; of <<= 1) {
                int u = __shfl_up_sync(0xffffffffu, x, of);
                if (lane >= of) x += u;
            }
            wsum[lane] = x;
        }
        __syncthreads();

        int carry = carry_s;
        int thrbase = carry + (wp ? wsum[wp - 1] : 0) + s - T;
        int4 r0 = make_int4(thrbase, thrbase + p0, thrbase + p1, thrbase + p2);
        int4 r1 = make_int4(thrbase + p3, thrbase + p4, thrbase + p5, thrbase + p6);
        *(int4*)(g_rowptr + o) = r0;
        *(int4*)(g_rowptr + o + 4) = r1;
        *(int4*)(g_cursor + o) = r0;
        *(int4*)(g_cursor + o + 4) = r1;
        __syncthreads();                  // all threads have read carry_s
        if (t == SCAN_THREADS - 1) carry_s = carry + wsum[31];
        __syncthreads();
    }
    if (t == 0) g_rowptr[NN] = carry_s;   // == EE (padding is zeros)
}

__global__ void reorder_kernel() {
    int idx = blockIdx.x * blockDim.x + threadIdx.x;
    int stride = gridDim.x * blockDim.x;
    for (int e = idx; e < EE; e += stride) {
        int d = g_dst[e];
        int pos = atomicAdd(&g_cursor[d], 1);
        g_ssrc[pos] = g_src[e];
    }
}

// ---------------- CSR gather aggregation ----------------
__global__ __launch_bounds__(256) void aggregate_kernel() {
    int w = (blockIdx.x * blockDim.x + threadIdx.x) >> 5;
    int lane = threadIdx.x & 31;
    if (w >= NN) return;
    int beg = g_rowptr[w];
    int end = g_rowptr[w + 1];
    const float4* hv = (const float4*)g_h;
    float4 acc = hv[(size_t)w * 32 + lane];
    int e = beg;
    for (; e + 4 <= end; e += 4) {
        int s0 = g_ssrc[e];
        int s1 = g_ssrc[e + 1];
        int s2 = g_ssrc[e + 2];
        int s3 = g_ssrc[e + 3];
        float4 a = hv[(size_t)s0 * 32 + lane];
        float4 b = hv[(size_t)s1 * 32 + lane];
        float4 c = hv[(size_t)s2 * 32 + lane];
        float4 d = hv[(size_t)s3 * 32 + lane];
        acc.x += (a.x + b.x) + (c.x + d.x);
        acc.y += (a.y + b.y) + (c.y + d.y);
        acc.z += (a.z + b.z) + (c.z + d.z);
        acc.w += (a.w + b.w) + (c.w + d.w);
    }
    for (; e < end; e++) {
        int s = g_ssrc[e];
        float4 a = hv[(size_t)s * 32 + lane];
        acc.x += a.x; acc.y += a.y; acc.z += a.z; acc.w += a.w;
    }
    ((float4*)g_agg)[(size_t)w * 32 + lane] = acc;
}

// ================= 3xTF32 mma.sync GEMM, hi/lo staged in SMEM; mode-2 fuses BN stats =================
#define GP 36
#define TILE_F (128 * GP)
#define GEMM_SMEM (4 * TILE_F * 4)

__global__ __launch_bounds__(256, 2) void gemm_mma(
    const float* __restrict__ Xext, const float* __restrict__ W,
    const float* __restrict__ bias, int M, int mode)
{
    extern __shared__ float dsm[];
    uint32_t* Xh = (uint32_t*)dsm;
    uint32_t* Xl = Xh + TILE_F;
    uint32_t* Wh = Xh + 2 * TILE_F;
    uint32_t* Wl = Xh + 3 * TILE_F;

    int t = threadIdx.x;
    int row0 = blockIdx.x << 7;

    if (mode == 1 && blockIdx.x == 0 && t < 128) { g_bnsum[t] = 0.f; g_bnsq[t] = 0.f; }

    const float* X = (mode == 0) ? Xext : ((mode == 1) ? g_agg : g_t);
    float* out = (mode == 0) ? g_h : ((mode == 1) ? g_t : g_z);

    int wid = t >> 5;
    int lane = t & 31;
    int gid = lane >> 2;
    int tid4 = lane & 3;
    int wr = wid & 3;
    int wc = wid >> 2;

    float acc[2][8][4];
#pragma unroll
    for (int mt = 0; mt < 2; mt++)
#pragma unroll
        for (int nt = 0; nt < 8; nt++)
#pragma unroll
            for (int j = 0; j < 4; j++) acc[mt][nt][j] = 0.f;

    for (int kc = 0; kc < 128; kc += 32) {
#pragma unroll
        for (int i = 0; i < 4; i++) {
            int f = t + i * 256;
            int r = f >> 3;
            int c4 = (f & 7) << 2;
            float4 xv = make_float4(0.f, 0.f, 0.f, 0.f);
            if (row0 + r < M)
                xv = *(const float4*)(X + (size_t)(row0 + r) * DD + kc + c4);
            uint4 hi, lo;
            hi.x = f2tf32(xv.x); lo.x = f2tf32(xv.x - __uint_as_float(hi.x));
            hi.y = f2tf32(xv.y); lo.y = f2tf32(xv.y - __uint_as_float(hi.y));
            hi.z = f2tf32(xv.z); lo.z = f2tf32(xv.z - __uint_as_float(hi.z));
            hi.w = f2tf32(xv.w); lo.w = f2tf32(xv.w - __uint_as_float(hi.w));
            *(uint4*)(Xh + r * GP + c4) = hi;
            *(uint4*)(Xl + r * GP + c4) = lo;
            float4 wv = *(const float4*)(W + (size_t)r * DD + kc + c4);
            hi.x = f2tf32(wv.x); lo.x = f2tf32(wv.x - __uint_as_float(hi.x));
            hi.y = f2tf32(wv.y); lo.y = f2tf32(wv.y - __uint_as_float(hi.y));
            hi.z = f2tf32(wv.z); lo.z = f2tf32(wv.z - __uint_as_float(hi.z));
            hi.w = f2tf32(wv.w); lo.w = f2tf32(wv.w - __uint_as_float(hi.w));
            *(uint4*)(Wh + r * GP + c4) = hi;
            *(uint4*)(Wl + r * GP + c4) = lo;
        }
        __syncthreads();

#pragma unroll
        for (int ks = 0; ks < 4; ks++) {
            int k0 = ks * 8;
            uint32_t ah[2][4], al[2][4];
#pragma unroll
            for (int mt = 0; mt < 2; mt++) {
                int rb = wr * 32 + mt * 16 + gid;
                ah[mt][0] = Xh[rb * GP + k0 + tid4];
                ah[mt][1] = Xh[(rb + 8) * GP + k0 + tid4];
                ah[mt][2] = Xh[rb * GP + k0 + tid4 + 4];
                ah[mt][3] = Xh[(rb + 8) * GP + k0 + tid4 + 4];
                al[mt][0] = Xl[rb * GP + k0 + tid4];
                al[mt][1] = Xl[(rb + 8) * GP + k0 + tid4];
                al[mt][2] = Xl[rb * GP + k0 + tid4 + 4];
                al[mt][3] = Xl[(rb + 8) * GP + k0 + tid4 + 4];
            }
#pragma unroll
            for (int nt = 0; nt < 8; nt++) {
                int cb = wc * 64 + nt * 8 + gid;
                uint32_t bh0 = Wh[cb * GP + k0 + tid4];
                uint32_t bh1 = Wh[cb * GP + k0 + tid4 + 4];
                uint32_t bl0 = Wl[cb * GP + k0 + tid4];
                uint32_t bl1 = Wl[cb * GP + k0 + tid4 + 4];
#pragma unroll
                for (int mt = 0; mt < 2; mt++) {
                    mma_tf32(acc[mt][nt], ah[mt][0], ah[mt][1], ah[mt][2], ah[mt][3], bh0, bh1);
                    mma_tf32(acc[mt][nt], ah[mt][0], ah[mt][1], ah[mt][2], ah[mt][3], bl0, bl1);
                    mma_tf32(acc[mt][nt], al[mt][0], al[mt][1], al[mt][2], al[mt][3], bh0, bh1);
                }
            }
        }
        __syncthreads();
    }

    // BN stats staging area (mode 2): dsm[0:128)=sum, dsm[128:256)=sumsq
    if (mode == 2) {
        if (t < 256) dsm[t] = 0.f;
        __syncthreads();
    }

    // epilogue (nt-outer so mode-2 column partials reduce in registers)
#pragma unroll
    for (int nt = 0; nt < 8; nt++) {
        int c = wc * 64 + nt * 8 + tid4 * 2;
        float2 bv = *(const float2*)(bias + c);
        float s0 = 0.f, s1 = 0.f, q0 = 0.f, q1 = 0.f;
#pragma unroll
        for (int mt = 0; mt < 2; mt++) {
            int r = row0 + wr * 32 + mt * 16 + gid;
            float2 v0, v1;
            v0.x = acc[mt][nt][0] + bv.x;
            v0.y = acc[mt][nt][1] + bv.y;
            v1.x = acc[mt][nt][2] + bv.x;
            v1.y = acc[mt][nt][3] + bv.y;
            if (mode == 1) {
                v0.x = fmaxf(v0.x, 0.f); v0.y = fmaxf(v0.y, 0.f);
                v1.x = fmaxf(v1.x, 0.f); v1.y = fmaxf(v1.y, 0.f);
            }
            if (r < M) {
                *(float2*)(out + (size_t)r * DD + c) = v0;
                if (mode == 2) { s0 += v0.x; s1 += v0.y; q0 += v0.x * v0.x; q1 += v0.y * v0.y; }
            }
            if (r + 8 < M) {
                *(float2*)(out + (size_t)(r + 8) * DD + c) = v1;
                if (mode == 2) { s0 += v1.x; s1 += v1.y; q0 += v1.x * v1.x; q1 += v1.y * v1.y; }
            }
        }
        if (mode == 2) {
            // reduce across gid (lanes stride 4); result lands on lanes 0..3
#pragma unroll
            for (int o = 16; o >= 4; o >>= 1) {
                s0 += __shfl_down_sync(0xffffffffu, s0, o);
                s1 += __shfl_down_sync(0xffffffffu, s1, o);
                q0 += __shfl_down_sync(0xffffffffu, q0, o);
                q1 += __shfl_down_sync(0xffffffffu, q1, o);
            }
            if (lane < 4) {
                atomicAdd(&dsm[c], s0);
                atomicAdd(&dsm[c + 1], s1);
                atomicAdd(&dsm[128 + c], q0);
                atomicAdd(&dsm[128 + c + 1], q1);
            }
        }
    }

    if (mode == 2) {
        __syncthreads();
        if (t < 128) {
            atomicAdd(&g_bnsum[t], dsm[t]);
            atomicAdd(&g_bnsq[t], dsm[128 + t]);
        }
    }
}

// ---------------- BN apply + relu (finalize fused: per-block scale/shift recompute) ----------------
__global__ void bn_apply_kernel(const float* __restrict__ gamma, const float* __restrict__ beta) {
    __shared__ float ssc[DD], ssh[DD];
    int t = threadIdx.x;
    if (t < DD) {
        float mu = g_bnsum[t] * (1.f / NN);
        float var = g_bnsq[t] * (1.f / NN) - mu * mu;
        float sc = gamma[t] * rsqrtf(var + BN_EPS_F);
        ssc[t] = sc;
        ssh[t] = beta[t] - mu * sc;
    }
    __syncthreads();
    int idx = blockIdx.x * blockDim.x + t;
    int stride = gridDim.x * blockDim.x;
    int total = NN * DD / 4;
    for (int i = idx; i < total; i += stride) {
        int cb = (i << 2) & (DD - 1);
        float4 z = *(const float4*)(&g_z[(size_t)i * 4]);
        float4 sc = *(const float4*)(&ssc[cb]);
        float4 sh = *(const float4*)(&ssh[cb]);
        float4 r;
        r.x = fmaxf(fmaf(z.x, sc.x, sh.x), 0.f);
        r.y = fmaxf(fmaf(z.y, sc.y, sh.y), 0.f);
        r.z = fmaxf(fmaf(z.z, sc.z, sh.z), 0.f);
        r.w = fmaxf(fmaf(z.w, sc.w, sh.w), 0.f);
        *(float4*)(&g_h[(size_t)i * 4]) = r;
    }
}

// ---------------- graph pooling ----------------
__global__ void zero_pooled_kernel() {
    int idx = blockIdx.x * blockDim.x + threadIdx.x;
    int stride = gridDim.x * blockDim.x;
    for (int i = idx; i < GG * DD; i += stride) g_pooled[i] = 0.f;
}

__global__ void pool_kernel() {
    int lane = threadIdx.x & 31;
    int w = (blockIdx.x * blockDim.x + threadIdx.x) >> 5;
    int nw = (gridDim.x * blockDim.x) >> 5;
    for (int n = w; n < NN; n += nw) {
        int g = g_batch[n];
        float4 v = *(const float4*)(g_h + (size_t)n * DD + (lane << 2));
        float* p = g_pooled + (size_t)g * DD + (lane << 2);
        atomicAdd(p + 0, v.x);
        atomicAdd(p + 1, v.y);
        atomicAdd(p + 2, v.z);
        atomicAdd(p + 3, v.w);
    }
}

// ---------------- final MLP ----------------
__global__ void final_kernel(const float* __restrict__ w1, const float* __restrict__ b1,
                             const float* __restrict__ w2, const float* __restrict__ b2,
                             float* __restrict__ out)
{
    __shared__ float row[DD];
    __shared__ float wsum[4];
    int g = blockIdx.x;
    int t = threadIdx.x;
    int lane = t & 31, warp = t >> 5;

    row[t] = g_pooled[(size_t)g * DD + t];
    __syncthreads();

    float4 r = *(const float4*)(&row[lane * 4]);
    float accum = 0.f;
    for (int c = warp; c < DD; c += 4) {
        float4 a = *(const float4*)(w1 + (size_t)c * DD + lane * 4);
        float p = a.x * r.x + a.y * r.y + a.z * r.z + a.w * r.w;
#pragma unroll
        for (int off = 16; off; off >>= 1) p += __shfl_down_sync(0xffffffffu, p, off);
        if (lane == 0) accum += fmaxf(p + b1[c], 0.f) * w2[c];
    }
    if (lane == 0) wsum[warp] = accum;
    __syncthreads();
    if (t == 0) out[g] = wsum[0] + wsum[1] + wsum[2] + wsum[3] + b2[0];
}

// ---------------- launch ----------------
extern "C" void kernel_launch(void* const* d_in, const int* in_sizes, int n_in,
                              void* d_out, int out_size)
{
    const float* x        = (const float*)d_in[0];
    const void*  ei       = d_in[1];
    const void*  batch    = d_in[2];
    const float* lin_w    = (const float*)d_in[3];
    const float* lin_b    = (const float*)d_in[4];
    const float* conv_w1  = (const float*)d_in[5];
    const float* conv_b1  = (const float*)d_in[6];
    const float* conv_w2  = (const float*)d_in[7];
    const float* conv_b2  = (const float*)d_in[8];
    const float* bn_gamma = (const float*)d_in[9];
    const float* bn_beta  = (const float*)d_in[10];
    const float* mlp_w1   = (const float*)d_in[11];
    const float* mlp_b1   = (const float*)d_in[12];
    const float* mlp_w2   = (const float*)d_in[13];
    const float* mlp_b2   = (const float*)d_in[14];
    float* out = (float*)d_out;

    static int smem_set = 0;
    if (!smem_set) {
        cudaFuncSetAttribute(gemm_mma, cudaFuncAttributeMaxDynamicSharedMemorySize, GEMM_SMEM);
        smem_set = 1;
    }

    const int gblocks = (NN + 127) / 128;   // 391

    detect_kernel<<<1, 128>>>((const unsigned int*)ei);               // 1
    zero_deg_kernel<<<(DEG_PAD + 255) / 256, 256>>>();                // 2
    convert_kernel<<<4096, 256>>>(ei, batch);                         // 3 (fused hist)
    gemm_mma<<<gblocks, 256, GEMM_SMEM>>>(x, lin_w, lin_b, NN, 0);    // 4 <- profile slot
    scan_kernel<<<1, SCAN_THREADS>>>();                               // 5
    reorder_kernel<<<2048, 256>>>();                                  // 6

    const int ablocks = (NN * 32 + 255) / 256;
    for (int i = 0; i < LL; i++) {
        aggregate_kernel<<<ablocks, 256>>>();
        gemm_mma<<<gblocks, 256, GEMM_SMEM>>>(nullptr, conv_w1 + (size_t)i * DD * DD, conv_b1 + i * DD, NN, 1);
        gemm_mma<<<gblocks, 256, GEMM_SMEM>>>(nullptr, conv_w2 + (size_t)i * DD * DD, conv_b2 + i * DD, NN, 2);
        bn_apply_kernel<<<4096, 256>>>(bn_gamma + i * DD, bn_beta + i * DD);
    }

    zero_pooled_kernel<<<1024, 256>>>();
    pool_kernel<<<1024, 256>>>();
    final_kernel<<<GG, 128>>>(mlp_w1, mlp_b1, mlp_w2, mlp_b2, out);
}

// round 17
// speedup vs baseline: 1.2651x; 1.1126x over previous
#include <cuda_runtime.h>
#include <cuda_bf16.h>
#include <math.h>
#include <stdint.h>

#define NN 50000
#define EE 1600000
#define DD 128
#define LL 5
#define GG 2048
#define BN_EPS_F 1e-5f

#define DEG_PAD 57344          // 1024 threads * 8 elems * 7 iters

// ---------------- scratch (static device globals; no allocation) ----------------
__device__ float g_h[NN * DD];
__device__ float g_agg[NN * DD];
__device__ float g_t[NN * DD];
__device__ float g_z[NN * DD];
__device__ int   g_src[EE];
__device__ int   g_dst[EE];
__device__ int   g_ssrc[EE];
__device__ int   g_deg[DEG_PAD];
__device__ int   g_rowptr[DEG_PAD + 8];
__device__ int   g_cursor[DEG_PAD];
__device__ int   g_batch[NN];
__device__ float g_pooled[GG * DD];
__device__ float g_bnsum[DD];
__device__ float g_bnsq[DD];
__device__ int   g_is32;

// ---------------- bf16 helpers ----------------
__device__ __forceinline__ void mma_bf16(float* d,
    uint32_t a0, uint32_t a1, uint32_t a2, uint32_t a3,
    uint32_t b0, uint32_t b1)
{
    asm volatile(
        "mma.sync.aligned.m16n8k16.row.col.f32.bf16.bf16.f32 "
        "{%0,%1,%2,%3}, {%4,%5,%6,%7}, {%8,%9}, {%0,%1,%2,%3};"
        : "+f"(d[0]), "+f"(d[1]), "+f"(d[2]), "+f"(d[3])
        : "r"(a0), "r"(a1), "r"(a2), "r"(a3), "r"(b0), "r"(b1));
}

// split float4 (4 consecutive K elems) into packed bf16 hi pair-words and lo pair-words
__device__ __forceinline__ void bf16_split4(float4 v, uint2& hi, uint2& lo) {
    __nv_bfloat162 h0 = __floats2bfloat162_rn(v.x, v.y);
    __nv_bfloat162 h1 = __floats2bfloat162_rn(v.z, v.w);
    float r0 = v.x - __bfloat162float(h0.x);
    float r1 = v.y - __bfloat162float(h0.y);
    float r2 = v.z - __bfloat162float(h1.x);
    float r3 = v.w - __bfloat162float(h1.y);
    __nv_bfloat162 l0 = __floats2bfloat162_rn(r0, r1);
    __nv_bfloat162 l1 = __floats2bfloat162_rn(r2, r3);
    hi.x = *reinterpret_cast<uint32_t*>(&h0);
    hi.y = *reinterpret_cast<uint32_t*>(&h1);
    lo.x = *reinterpret_cast<uint32_t*>(&l0);
    lo.y = *reinterpret_cast<uint32_t*>(&l1);
}

// ---------------- dtype detection ----------------
__global__ void detect_kernel(const unsigned int* __restrict__ w) {
    __shared__ int any;
    if (threadIdx.x == 0) any = 0;
    __syncthreads();
    if (w[threadIdx.x * 2 + 1] != 0u) any = 1;
    __syncthreads();
    if (threadIdx.x == 0) g_is32 = any;
}

__global__ void zero_deg_kernel() {
    int idx = blockIdx.x * blockDim.x + threadIdx.x;
    if (idx < DEG_PAD) g_deg[idx] = 0;
}

// converts edge_index + batch AND histograms dst into g_deg
__global__ void convert_kernel(const void* __restrict__ ei, const void* __restrict__ batch) {
    int idx = blockIdx.x * blockDim.x + threadIdx.x;
    int stride = gridDim.x * blockDim.x;
    int is32 = g_is32;
    int total = EE + NN;
    for (int i = idx; i < total; i += stride) {
        if (i < EE) {
            int s, d;
            if (is32) {
                const int* p = (const int*)ei;
                s = p[i]; d = p[EE + i];
            } else {
                const long long* p = (const long long*)ei;
                s = (int)p[i]; d = (int)p[EE + i];
            }
            g_src[i] = s;
            g_dst[i] = d;
            atomicAdd(&g_deg[d], 1);
        } else {
            int n = i - EE;
            if (is32) g_batch[n] = ((const int*)batch)[n];
            else      g_batch[n] = (int)((const long long*)batch)[n];
        }
    }
}

// ---------------- scan v3: 8 elems/thread, int4, 7 iterations ----------------
#define SCAN_THREADS 1024
#define SCAN_ITERS 7
__global__ void scan_kernel() {
    __shared__ int wsum[32];
    __shared__ int carry_s;
    int t = threadIdx.x, lane = t & 31, wp = t >> 5;
    if (t == 0) carry_s = 0;
    __syncthreads();

#pragma unroll
    for (int iter = 0; iter < SCAN_ITERS; iter++) {
        int base = iter * (SCAN_THREADS * 8);
        int o = base + t * 8;
        int4 a = *(const int4*)(g_deg + o);
        int4 b = *(const int4*)(g_deg + o + 4);
        int p0 = a.x;
        int p1 = p0 + a.y;
        int p2 = p1 + a.z;
        int p3 = p2 + a.w;
        int p4 = p3 + b.x;
        int p5 = p4 + b.y;
        int p6 = p5 + b.z;
        int T  = p6 + b.w;

        int s = T;
#pragma unroll
        for (int of = 1; of < 32; of <<= 1) {
            int u = __shfl_up_sync(0xffffffffu, s, of);
            if (lane >= of) s += u;
        }
        if (lane == 31) wsum[wp] = s;
        __syncthreads();
        if (wp == 0) {
            int x = wsum[lane];
#pragma unroll
            for (int of = 1; of < 32; of <<= 1) {
                int u = __shfl_up_sync(0xffffffffu, x, of);
                if (lane >= of) x += u;
            }
            wsum[lane] = x;
        }
        __syncthreads();

        int carry = carry_s;
        int thrbase = carry + (wp ? wsum[wp - 1] : 0) + s - T;
        int4 r0 = make_int4(thrbase, thrbase + p0, thrbase + p1, thrbase + p2);
        int4 r1 = make_int4(thrbase + p3, thrbase + p4, thrbase + p5, thrbase + p6);
        *(int4*)(g_rowptr + o) = r0;
        *(int4*)(g_rowptr + o + 4) = r1;
        *(int4*)(g_cursor + o) = r0;
        *(int4*)(g_cursor + o + 4) = r1;
        __syncthreads();
        if (t == SCAN_THREADS - 1) carry_s = carry + wsum[31];
        __syncthreads();
    }
    if (t == 0) g_rowptr[NN] = carry_s;
}

__global__ void reorder_kernel() {
    int idx = blockIdx.x * blockDim.x + threadIdx.x;
    int stride = gridDim.x * blockDim.x;
    for (int e = idx; e < EE; e += stride) {
        int d = g_dst[e];
        int pos = atomicAdd(&g_cursor[d], 1);
        g_ssrc[pos] = g_src[e];
    }
}

// ---------------- CSR gather aggregation ----------------
__global__ __launch_bounds__(256) void aggregate_kernel() {
    int w = (blockIdx.x * blockDim.x + threadIdx.x) >> 5;
    int lane = threadIdx.x & 31;
    if (w >= NN) return;
    int beg = g_rowptr[w];
    int end = g_rowptr[w + 1];
    const float4* hv = (const float4*)g_h;
    float4 acc = hv[(size_t)w * 32 + lane];
    int e = beg;
    for (; e + 4 <= end; e += 4) {
        int s0 = g_ssrc[e];
        int s1 = g_ssrc[e + 1];
        int s2 = g_ssrc[e + 2];
        int s3 = g_ssrc[e + 3];
        float4 a = hv[(size_t)s0 * 32 + lane];
        float4 b = hv[(size_t)s1 * 32 + lane];
        float4 c = hv[(size_t)s2 * 32 + lane];
        float4 d = hv[(size_t)s3 * 32 + lane];
        acc.x += (a.x + b.x) + (c.x + d.x);
        acc.y += (a.y + b.y) + (c.y + d.y);
        acc.z += (a.z + b.z) + (c.z + d.z);
        acc.w += (a.w + b.w) + (c.w + d.w);
    }
    for (; e < end; e++) {
        int s = g_ssrc[e];
        float4 a = hv[(size_t)s * 32 + lane];
        acc.x += a.x; acc.y += a.y; acc.z += a.z; acc.w += a.w;
    }
    ((float4*)g_agg)[(size_t)w * 32 + lane] = acc;
}

// ================= 3-product bf16 mma.sync GEMM (hi/lo split), K-chunks of 64 =================
// SMEM per buffer: 128 rows x (32 data + 4 pad) u32; 4 buffers = 73728 B.
// Packed layout: u32 j in a row holds bf16 K-elems (2j, 2j+1) of that chunk.
#define GP 36
#define TILE_F (128 * GP)
#define GEMM_SMEM (4 * TILE_F * 4)

__global__ __launch_bounds__(256, 2) void gemm_mma(
    const float* __restrict__ Xext, const float* __restrict__ W,
    const float* __restrict__ bias, int M, int mode)
{
    extern __shared__ float dsm[];
    uint32_t* Xh = (uint32_t*)dsm;
    uint32_t* Xl = Xh + TILE_F;
    uint32_t* Wh = Xh + 2 * TILE_F;
    uint32_t* Wl = Xh + 3 * TILE_F;

    int t = threadIdx.x;
    int row0 = blockIdx.x << 7;

    if (mode == 1 && blockIdx.x == 0 && t < 128) { g_bnsum[t] = 0.f; g_bnsq[t] = 0.f; }

    const float* X = (mode == 0) ? Xext : ((mode == 1) ? g_agg : g_t);
    float* out = (mode == 0) ? g_h : ((mode == 1) ? g_t : g_z);

    int wid = t >> 5;
    int lane = t & 31;
    int gid = lane >> 2;
    int tid4 = lane & 3;
    int wr = wid & 3;
    int wc = wid >> 2;

    float acc[2][8][4];
#pragma unroll
    for (int mt = 0; mt < 2; mt++)
#pragma unroll
        for (int nt = 0; nt < 8; nt++)
#pragma unroll
            for (int j = 0; j < 4; j++) acc[mt][nt][j] = 0.f;

    for (int kc = 0; kc < 128; kc += 64) {
        // stage 64-K chunk: 128 rows x 16 float4 = 2048 float4 per matrix; 8 iters x 256 thr
#pragma unroll
        for (int i = 0; i < 8; i++) {
            int f = t + i * 256;           // 0..2047
            int r = f >> 4;                // 0..127
            int c4 = (f & 15) << 2;        // float offset in chunk: 0,4,...,60
            int u = (c4 >> 1);             // u32 offset: 0,2,...,30 (uint2-aligned)
            float4 xv = make_float4(0.f, 0.f, 0.f, 0.f);
            if (row0 + r < M)
                xv = *(const float4*)(X + (size_t)(row0 + r) * DD + kc + c4);
            uint2 hi, lo;
            bf16_split4(xv, hi, lo);
            *(uint2*)(Xh + r * GP + u) = hi;
            *(uint2*)(Xl + r * GP + u) = lo;
            float4 wv = *(const float4*)(W + (size_t)r * DD + kc + c4);
            bf16_split4(wv, hi, lo);
            *(uint2*)(Wh + r * GP + u) = hi;
            *(uint2*)(Wl + r * GP + u) = lo;
        }
        __syncthreads();

#pragma unroll
        for (int ks = 0; ks < 4; ks++) {    // 4 k-steps of 16 bf16 (8 u32) each
            int k0 = ks * 8;
            uint32_t ah[2][4], al[2][4];
#pragma unroll
            for (int mt = 0; mt < 2; mt++) {
                int rb = wr * 32 + mt * 16 + gid;
                ah[mt][0] = Xh[rb * GP + k0 + tid4];
                ah[mt][1] = Xh[(rb + 8) * GP + k0 + tid4];
                ah[mt][2] = Xh[rb * GP + k0 + tid4 + 4];
                ah[mt][3] = Xh[(rb + 8) * GP + k0 + tid4 + 4];
                al[mt][0] = Xl[rb * GP + k0 + tid4];
                al[mt][1] = Xl[(rb + 8) * GP + k0 + tid4];
                al[mt][2] = Xl[rb * GP + k0 + tid4 + 4];
                al[mt][3] = Xl[(rb + 8) * GP + k0 + tid4 + 4];
            }
#pragma unroll
            for (int nt = 0; nt < 8; nt++) {
                int cb = wc * 64 + nt * 8 + gid;
                uint32_t bh0 = Wh[cb * GP + k0 + tid4];
                uint32_t bh1 = Wh[cb * GP + k0 + tid4 + 4];
                uint32_t bl0 = Wl[cb * GP + k0 + tid4];
                uint32_t bl1 = Wl[cb * GP + k0 + tid4 + 4];
#pragma unroll
                for (int mt = 0; mt < 2; mt++) {
                    mma_bf16(acc[mt][nt], ah[mt][0], ah[mt][1], ah[mt][2], ah[mt][3], bh0, bh1);
                    mma_bf16(acc[mt][nt], ah[mt][0], ah[mt][1], ah[mt][2], ah[mt][3], bl0, bl1);
                    mma_bf16(acc[mt][nt], al[mt][0], al[mt][1], al[mt][2], al[mt][3], bh0, bh1);
                }
            }
        }
        __syncthreads();
    }

    // BN stats staging (mode 2)
    if (mode == 2) {
        if (t < 256) dsm[t] = 0.f;
        __syncthreads();
    }

    // epilogue: c0:(r, c) c1:(r, c+1) c2:(r+8, c) c3:(r+8, c+1)
#pragma unroll
    for (int nt = 0; nt < 8; nt++) {
        int c = wc * 64 + nt * 8 + tid4 * 2;
        float2 bv = *(const float2*)(bias + c);
        float s0 = 0.f, s1 = 0.f, q0 = 0.f, q1 = 0.f;
#pragma unroll
        for (int mt = 0; mt < 2; mt++) {
            int r = row0 + wr * 32 + mt * 16 + gid;
            float2 v0, v1;
            v0.x = acc[mt][nt][0] + bv.x;
            v0.y = acc[mt][nt][1] + bv.y;
            v1.x = acc[mt][nt][2] + bv.x;
            v1.y = acc[mt][nt][3] + bv.y;
            if (mode == 1) {
                v0.x = fmaxf(v0.x, 0.f); v0.y = fmaxf(v0.y, 0.f);
                v1.x = fmaxf(v1.x, 0.f); v1.y = fmaxf(v1.y, 0.f);
            }
            if (r < M) {
                *(float2*)(out + (size_t)r * DD + c) = v0;
                if (mode == 2) { s0 += v0.x; s1 += v0.y; q0 += v0.x * v0.x; q1 += v0.y * v0.y; }
            }
            if (r + 8 < M) {
                *(float2*)(out + (size_t)(r + 8) * DD + c) = v1;
                if (mode == 2) { s0 += v1.x; s1 += v1.y; q0 += v1.x * v1.x; q1 += v1.y * v1.y; }
            }
        }
        if (mode == 2) {
#pragma unroll
            for (int o = 16; o >= 4; o >>= 1) {
                s0 += __shfl_down_sync(0xffffffffu, s0, o);
                s1 += __shfl_down_sync(0xffffffffu, s1, o);
                q0 += __shfl_down_sync(0xffffffffu, q0, o);
                q1 += __shfl_down_sync(0xffffffffu, q1, o);
            }
            if (lane < 4) {
                atomicAdd(&dsm[c], s0);
                atomicAdd(&dsm[c + 1], s1);
                atomicAdd(&dsm[128 + c], q0);
                atomicAdd(&dsm[128 + c + 1], q1);
            }
        }
    }

    if (mode == 2) {
        __syncthreads();
        if (t < 128) {
            atomicAdd(&g_bnsum[t], dsm[t]);
            atomicAdd(&g_bnsq[t], dsm[128 + t]);
        }
    }
}

// ---------------- BN apply + relu (finalize fused per-block) ----------------
__global__ void bn_apply_kernel(const float* __restrict__ gamma, const float* __restrict__ beta) {
    __shared__ float ssc[DD], ssh[DD];
    int t = threadIdx.x;
    if (t < DD) {
        float mu = g_bnsum[t] * (1.f / NN);
        float var = g_bnsq[t] * (1.f / NN) - mu * mu;
        float sc = gamma[t] * rsqrtf(var + BN_EPS_F);
        ssc[t] = sc;
        ssh[t] = beta[t] - mu * sc;
    }
    __syncthreads();
    int idx = blockIdx.x * blockDim.x + t;
    int stride = gridDim.x * blockDim.x;
    int total = NN * DD / 4;
    for (int i = idx; i < total; i += stride) {
        int cb = (i << 2) & (DD - 1);
        float4 z = *(const float4*)(&g_z[(size_t)i * 4]);
        float4 sc = *(const float4*)(&ssc[cb]);
        float4 sh = *(const float4*)(&ssh[cb]);
        float4 r;
        r.x = fmaxf(fmaf(z.x, sc.x, sh.x), 0.f);
        r.y = fmaxf(fmaf(z.y, sc.y, sh.y), 0.f);
        r.z = fmaxf(fmaf(z.z, sc.z, sh.z), 0.f);
        r.w = fmaxf(fmaf(z.w, sc.w, sh.w), 0.f);
        *(float4*)(&g_h[(size_t)i * 4]) = r;
    }
}

// ---------------- graph pooling ----------------
__global__ void zero_pooled_kernel() {
    int idx = blockIdx.x * blockDim.x + threadIdx.x;
    int stride = gridDim.x * blockDim.x;
    for (int i = idx; i < GG * DD; i += stride) g_pooled[i] = 0.f;
}

__global__ void pool_kernel() {
    int lane = threadIdx.x & 31;
    int w = (blockIdx.x * blockDim.x + threadIdx.x) >> 5;
    int nw = (gridDim.x * blockDim.x) >> 5;
    for (int n = w; n < NN; n += nw) {
        int g = g_batch[n];
        float4 v = *(const float4*)(g_h + (size_t)n * DD + (lane << 2));
        float* p = g_pooled + (size_t)g * DD + (lane << 2);
        atomicAdd(p + 0, v.x);
        atomicAdd(p + 1, v.y);
        atomicAdd(p + 2, v.z);
        atomicAdd(p + 3, v.w);
    }
}

// ---------------- final MLP ----------------
__global__ void final_kernel(const float* __restrict__ w1, const float* __restrict__ b1,
                             const float* __restrict__ w2, const float* __restrict__ b2,
                             float* __restrict__ out)
{
    __shared__ float row[DD];
    __shared__ float wsum[4];
    int g = blockIdx.x;
    int t = threadIdx.x;
    int lane = t & 31, warp = t >> 5;

    row[t] = g_pooled[(size_t)g * DD + t];
    __syncthreads();

    float4 r = *(const float4*)(&row[lane * 4]);
    float accum = 0.f;
    for (int c = warp; c < DD; c += 4) {
        float4 a = *(const float4*)(w1 + (size_t)c * DD + lane * 4);
        float p = a.x * r.x + a.y * r.y + a.z * r.z + a.w * r.w;
#pragma unroll
        for (int off = 16; off; off >>= 1) p += __shfl_down_sync(0xffffffffu, p, off);
        if (lane == 0) accum += fmaxf(p + b1[c], 0.f) * w2[c];
    }
    if (lane == 0) wsum[warp] = accum;
    __syncthreads();
    if (t == 0) out[g] = wsum[0] + wsum[1] + wsum[2] + wsum[3] + b2[0];
}

// ---------------- launch ----------------
extern "C" void kernel_launch(void* const* d_in, const int* in_sizes, int n_in,
                              void* d_out, int out_size)
{
    const float* x        = (const float*)d_in[0];
    const void*  ei       = d_in[1];
    const void*  batch    = d_in[2];
    const float* lin_w    = (const float*)d_in[3];
    const float* lin_b    = (const float*)d_in[4];
    const float* conv_w1  = (const float*)d_in[5];
    const float* conv_b1  = (const float*)d_in[6];
    const float* conv_w2  = (const float*)d_in[7];
    const float* conv_b2  = (const float*)d_in[8];
    const float* bn_gamma = (const float*)d_in[9];
    const float* bn_beta  = (const float*)d_in[10];
    const float* mlp_w1   = (const float*)d_in[11];
    const float* mlp_b1   = (const float*)d_in[12];
    const float* mlp_w2   = (const float*)d_in[13];
    const float* mlp_b2   = (const float*)d_in[14];
    float* out = (float*)d_out;

    static int smem_set = 0;
    if (!smem_set) {
        cudaFuncSetAttribute(gemm_mma, cudaFuncAttributeMaxDynamicSharedMemorySize, GEMM_SMEM);
        smem_set = 1;
    }

    const int gblocks = (NN + 127) / 128;   // 391

    detect_kernel<<<1, 128>>>((const unsigned int*)ei);               // 1
    zero_deg_kernel<<<(DEG_PAD + 255) / 256, 256>>>();                // 2
    convert_kernel<<<4096, 256>>>(ei, batch);                         // 3 (fused hist)
    gemm_mma<<<gblocks, 256, GEMM_SMEM>>>(x, lin_w, lin_b, NN, 0);    // 4 <- profile slot
    scan_kernel<<<1, SCAN_THREADS>>>();                               // 5
    reorder_kernel<<<2048, 256>>>();                                  // 6

    const int ablocks = (NN * 32 + 255) / 256;
    for (int i = 0; i < LL; i++) {
        aggregate_kernel<<<ablocks, 256>>>();
        gemm_mma<<<gblocks, 256, GEMM_SMEM>>>(nullptr, conv_w1 + (size_t)i * DD * DD, conv_b1 + i * DD, NN, 1);
        gemm_mma<<<gblocks, 256, GEMM_SMEM>>>(nullptr, conv_w2 + (size_t)i * DD * DD, conv_b2 + i * DD, NN, 2);
        bn_apply_kernel<<<4096, 256>>>(bn_gamma + i * DD, bn_beta + i * DD);
    }

    zero_pooled_kernel<<<1024, 256>>>();
    pool_kernel<<<1024, 256>>>();
    final_kernel<<<GG, 128>>>(mlp_w1, mlp_b1, mlp_w2, mlp_b2, out);
}